// round 6
// baseline (speedup 1.0000x reference)
#include <cuda_runtime.h>
#include <cuda_bf16.h>
#include <mma.h>
#include <math.h>
#include <cstdint>

using namespace nvcuda;

#define DIM 2048
#define H 16
#define KVH 4
#define HD 128
#define RD 64
#define BATCH 4
#define T 2048
#define MTOT (BATCH * T)   // 8192
#define SCALE 0.08838834764831845f
#define LOG2_10000 13.287712379549449f

// ---------------- scratch -----------------------------------------------------
__device__ float g_qlin[MTOT * DIM];
__device__ float g_klin[MTOT * KVH * HD];
__device__ float g_vlin[MTOT * KVH * HD];
__device__ float g_q[BATCH * H * T * HD];
__device__ float g_k[BATCH * KVH * T * HD];
__device__ float g_v[BATCH * KVH * T * HD];
__device__ float g_y[MTOT * DIM];
__device__ float g_xt[MTOT * DIM];
__device__ float g_wqt[DIM * DIM];
__device__ float g_wkt[KVH * HD * DIM];
__device__ float g_wvt[KVH * HD * DIM];
__device__ float g_wpt[DIM * DIM];

// ---------------- helpers ------------------------------------------------------
__device__ __forceinline__ float to_tf32(float x) {
    float r;
    asm("cvt.rna.tf32.f32 %0, %1;\n" : "=f"(r) : "f"(x));
    return r;
}
__device__ __forceinline__ void cp_async16(void* smem, const void* gmem) {
    unsigned s = (unsigned)__cvta_generic_to_shared(smem);
    asm volatile("cp.async.cg.shared.global [%0], [%1], 16;\n" :: "r"(s), "l"(gmem) : "memory");
}
#define CP_COMMIT asm volatile("cp.async.commit_group;\n" ::: "memory")
#define CP_WAIT0  asm volatile("cp.async.wait_group 0;\n" ::: "memory")
#define CP_WAIT1  asm volatile("cp.async.wait_group 1;\n" ::: "memory")
#define CP_WAIT2  asm volatile("cp.async.wait_group 2;\n" ::: "memory")

// ---------------- fused tf32 truncation ---------------------------------------
#define N4X 4194304
#define N4Q 1048576
#define N4K 262144
#define N4V 262144
#define N4P 1048576
__global__ void convert_all(
    const float* __restrict__ x, const float* __restrict__ wq,
    const float* __restrict__ wk, const float* __restrict__ wv,
    const float* __restrict__ wp,
    float* __restrict__ xt, float* __restrict__ wqt,
    float* __restrict__ wkt, float* __restrict__ wvt, float* __restrict__ wpt)
{
    int i = blockIdx.x * blockDim.x + threadIdx.x;
    const float4* src; float4* dst; int off;
    if (i < N4X)                         { src = (const float4*)x;  dst = (float4*)xt;  off = 0; }
    else if (i < N4X + N4Q)              { src = (const float4*)wq; dst = (float4*)wqt; off = N4X; }
    else if (i < N4X + N4Q + N4K)        { src = (const float4*)wk; dst = (float4*)wkt; off = N4X + N4Q; }
    else if (i < N4X + N4Q + N4K + N4V)  { src = (const float4*)wv; dst = (float4*)wvt; off = N4X + N4Q + N4K; }
    else                                 { src = (const float4*)wp; dst = (float4*)wpt; off = N4X + N4Q + N4K + N4V; }
    int j = i - off;
    float4 v = src[j];
    v.x = to_tf32(v.x); v.y = to_tf32(v.y);
    v.z = to_tf32(v.z); v.w = to_tf32(v.w);
    dst[j] = v;
}

// ---------------- TF32 GEMM, segmented N --------------------------------------
// BM=BN=128, BK=32, 4 warps (64x64 each), 3-stage cp.async, smem pad 36.
#define GSTRIDE 36
#define GSTAGE (128 * GSTRIDE)
#define GEMM_SMEM (3 * 2 * GSTAGE * 4)    // 110592 bytes

__global__ void __launch_bounds__(128, 2) gemm_seg(
    const float* __restrict__ A, int K,
    const float* __restrict__ B0, float* __restrict__ C0, int t0, int ldc0,
    const float* __restrict__ B1, float* __restrict__ C1, int t1, int ldc1,
    const float* __restrict__ B2, float* __restrict__ C2, int t2, int ldc2)
{
    extern __shared__ float smem[];
    const int tid = threadIdx.x;
    const int warp = tid >> 5;
    const int wr = warp >> 1, wc = warp & 1;
    const int bm = blockIdx.y;
    int bn = blockIdx.x;

    const float* B; float* C; int ldc;
    if (bn < t0)            { B = B0; C = C0; ldc = ldc0; }
    else if (bn < t0 + t1)  { B = B1; C = C1; ldc = ldc1; bn -= t0; }
    else                    { B = B2; C = C2; ldc = ldc2; bn -= t0 + t1; }

    const float* Ab = A + (size_t)bm * 128 * K;
    const float* Bb = B + (size_t)bn * 128 * K;

    wmma::fragment<wmma::accumulator, 16, 16, 8, float> acc[4][4];
#pragma unroll
    for (int i = 0; i < 4; i++)
#pragma unroll
        for (int j = 0; j < 4; j++) wmma::fill_fragment(acc[i][j], 0.0f);

    const int ntiles = K >> 5;
#pragma unroll
    for (int s = 0; s < 2; s++) {
        float* As = smem + s * 2 * GSTAGE;
        float* Bs = As + GSTAGE;
#pragma unroll
        for (int i = 0; i < 8; i++) {
            int idx = tid + i * 128;
            int r = idx >> 3, c = (idx & 7) * 4;
            cp_async16(As + r * GSTRIDE + c, Ab + (size_t)r * K + s * 32 + c);
            cp_async16(Bs + r * GSTRIDE + c, Bb + (size_t)r * K + s * 32 + c);
        }
        CP_COMMIT;
    }

    for (int kt = 0; kt < ntiles; kt++) {
        CP_WAIT1;
        __syncthreads();
        float* As = smem + (kt % 3) * 2 * GSTAGE;
        float* Bs = As + GSTAGE;
#pragma unroll
        for (int kk = 0; kk < 32; kk += 8) {
            wmma::fragment<wmma::matrix_a, 16, 16, 8, wmma::precision::tf32, wmma::row_major> a[4];
            wmma::fragment<wmma::matrix_b, 16, 16, 8, wmma::precision::tf32, wmma::col_major> bf[4];
#pragma unroll
            for (int i = 0; i < 4; i++)
                wmma::load_matrix_sync(a[i], As + (wr * 64 + i * 16) * GSTRIDE + kk, GSTRIDE);
#pragma unroll
            for (int j = 0; j < 4; j++)
                wmma::load_matrix_sync(bf[j], Bs + (wc * 64 + j * 16) * GSTRIDE + kk, GSTRIDE);
#pragma unroll
            for (int i = 0; i < 4; i++)
#pragma unroll
                for (int j = 0; j < 4; j++)
                    wmma::mma_sync(acc[i][j], a[i], bf[j], acc[i][j]);
        }
        __syncthreads();
        if (kt + 2 < ntiles) {
            int s = (kt + 2) % 3;
            int k0 = (kt + 2) * 32;
            float* An = smem + s * 2 * GSTAGE;
            float* Bn = An + GSTAGE;
#pragma unroll
            for (int i = 0; i < 8; i++) {
                int idx = tid + i * 128;
                int r = idx >> 3, c = (idx & 7) * 4;
                cp_async16(An + r * GSTRIDE + c, Ab + (size_t)r * K + k0 + c);
                cp_async16(Bn + r * GSTRIDE + c, Bb + (size_t)r * K + k0 + c);
            }
        }
        CP_COMMIT;
    }

#pragma unroll
    for (int i = 0; i < 4; i++)
#pragma unroll
        for (int j = 0; j < 4; j++)
            wmma::store_matrix_sync(
                C + (size_t)(bm * 128 + wr * 64 + i * 16) * ldc + bn * 128 + wc * 64 + j * 16,
                acc[i][j], ldc, wmma::mem_row_major);
}

// ---------------- fused RMSNorm+RoPE (q,k) + v reorder, tf32 out --------------
#define NWQ (BATCH * T * H)
#define NWK (BATCH * T * KVH)
#define NWV (BATCH * T * KVH)
__global__ void rope_fused(
    const float* __restrict__ qlin, const float* __restrict__ klin,
    const float* __restrict__ vlin, const float* __restrict__ gain,
    float* __restrict__ qout, float* __restrict__ kout, float* __restrict__ vout)
{
    int w = (blockIdx.x * blockDim.x + threadIdx.x) >> 5;
    int lane = threadIdx.x & 31;

    if (w < NWQ + NWK) {
        bool isq = (w < NWQ);
        int hh, t, b, nh;
        const float* src;
        if (isq) {
            nh = H;
            hh = w % H; t = (w / H) % T; b = w / (H * T);
            src = qlin + ((size_t)(b * T + t)) * DIM + hh * HD;
        } else {
            int wk = w - NWQ;
            nh = KVH;
            hh = wk % KVH; t = (wk / KVH) % T; b = wk / (KVH * T);
            src = klin + ((size_t)(b * T + t)) * (KVH * HD) + hh * HD;
        }
        float v0 = src[lane], v1 = src[lane + 32], v2 = src[lane + 64], v3 = src[lane + 96];
        float ss = v0 * v0 + v1 * v1 + v2 * v2 + v3 * v3;
#pragma unroll
        for (int o = 16; o; o >>= 1) ss += __shfl_xor_sync(0xffffffffu, ss, o);
        float r = rsqrtf(ss * (1.0f / 128.0f) + 1e-6f);
        v0 *= r; v1 *= r; v2 *= r; v3 *= r;

        float inv = exp2f(-(float)lane * (LOG2_10000 / 32.0f));
        float fr = (float)t * inv;
        float sn, cs;
        sincosf(fr, &sn, &cs);
        float o0 = v0 * cs - v1 * sn;
        float o1 = v1 * cs + v0 * sn;

        float g = isq ? gain[hh] * SCALE : 1.0f;
        float* dst = (isq ? qout : kout) + (((size_t)(b * nh + hh)) * T + t) * HD;
        dst[lane]      = to_tf32(o0 * g);
        dst[lane + 32] = to_tf32(o1 * g);
        dst[lane + 64] = to_tf32(v2 * g);
        dst[lane + 96] = to_tf32(v3 * g);
    } else {
        int u = w - NWQ - NWK;
        int kv = u & 3;
        int bt = u >> 2;
        int t = bt & (T - 1);
        int b = bt >> 11;
        float4 val = ((const float4*)vlin)[u * 32 + lane];
        val.x = to_tf32(val.x); val.y = to_tf32(val.y);
        val.z = to_tf32(val.z); val.w = to_tf32(val.w);
        ((float4*)(vout + (((size_t)(b * KVH + kv)) * T + t) * HD))[lane] = val;
    }
}

// ---------------- Flash attention (BQ=128, BKV=64, 512 threads) ---------------
// smem: Qs 0..64K | Ksm 64K..128K (2x) ->Osm | Vsm 128K..192K (2x) | SP 192K..226K | arow
#define FA_SMEM 231936

__global__ void __launch_bounds__(512, 1) flash_kernel(
    const float* __restrict__ Q, const float* __restrict__ Kg,
    const float* __restrict__ Vg, const float* __restrict__ vlin,
    float* __restrict__ Y)
{
    extern __shared__ char sm[];
    float* Qs   = (float*)sm;
    float* Ksm  = (float*)(sm + 65536);
    float* Vsm  = (float*)(sm + 131072);
    float* SP   = (float*)(sm + 196608);
    float* arow = (float*)(sm + 231424);
    float* Osm  = Ksm;

    const int tid = threadIdx.x;
    const int warp = tid >> 5;                 // 0..15
    const int wmS = warp >> 1, wnS = warp & 1; // S: 16-row x 32-col tiles
    const int wmP = warp >> 2, wnP = warp & 3; // PV/O: 32-row x 32-col tiles
    const int qi = (gridDim.x - 1) - blockIdx.x;
    const int h = blockIdx.y, b = blockIdx.z;
    const int q0 = qi * 128;
    const int kvh = h >> 2;
    const int njt = 2 * qi + 2;

    const float* Qbase = Q + (((size_t)b * H + h) * T + q0) * HD;
    const float* Kbase = Kg + ((size_t)b * KVH + kvh) * T * HD;
    const float* Vbase = Vg + ((size_t)b * KVH + kvh) * T * HD;

    // prologue: K0, V0 (2048 float4 each, 512 threads -> 4 each)
#pragma unroll
    for (int i = 0; i < 4; i++)
        cp_async16((float4*)Ksm + tid + i * 512, (const float4*)Kbase + tid + i * 512);
    CP_COMMIT;
#pragma unroll
    for (int i = 0; i < 4; i++)
        cp_async16((float4*)Vsm + tid + i * 512, (const float4*)Vbase + tid + i * 512);
    CP_COMMIT;

    // Q copy + probe pattern
    for (int i = tid; i < 4096; i += 512)
        ((float4*)Qs)[i] = ((const float4*)Qbase)[i];
    if (tid < 256) {
        int r = tid >> 4, c = tid & 15;
        SP[r * 68 + c] = (float)r;
    }
    __syncthreads();

    int rowmap[8];
    {
        wmma::fragment<wmma::accumulator, 16, 16, 8, float> probe;
        wmma::load_matrix_sync(probe, SP, 68, wmma::mem_row_major);
#pragma unroll
        for (int e = 0; e < 8; e++) rowmap[e] = (int)probe.x[e];
    }

    wmma::fragment<wmma::accumulator, 16, 16, 8, float> oacc[2][2];
#pragma unroll
    for (int i = 0; i < 2; i++)
#pragma unroll
        for (int n = 0; n < 2; n++) wmma::fill_fragment(oacc[i][n], 0.0f);

    const int r_sm = tid >> 2, sub = tid & 3;   // softmax: 4 threads/row, 16 cols each
    float m_state = -INFINITY, l_state = 0.f;

    for (int j = 0; j < njt; j++) {
        const int buf = j & 1;
        float* Ks = Ksm + buf * 8192;
        float* Vs = Vsm + buf * 8192;
        const int kbase = j * 64;

        if (j + 1 < njt) {
            float* Kn = Ksm + (buf ^ 1) * 8192;
            const float4* Kg4 = (const float4*)(Kbase + (size_t)(j + 1) * 8192);
#pragma unroll
            for (int i = 0; i < 4; i++)
                cp_async16((float4*)Kn + tid + i * 512, Kg4 + tid + i * 512);
            CP_COMMIT;
            CP_WAIT2;
        } else {
            CP_WAIT1;
        }
        __syncthreads();

        // S = Q @ K^T : warp -> rows [wmS*16, +16), cols [wnS*32, +32)
        {
            wmma::fragment<wmma::accumulator, 16, 16, 8, float> sacc[2];
            wmma::fill_fragment(sacc[0], 0.0f);
            wmma::fill_fragment(sacc[1], 0.0f);
#pragma unroll
            for (int kk = 0; kk < 128; kk += 8) {
                wmma::fragment<wmma::matrix_a, 16, 16, 8, wmma::precision::tf32, wmma::row_major> a;
                wmma::fragment<wmma::matrix_b, 16, 16, 8, wmma::precision::tf32, wmma::col_major> bb[2];
                wmma::load_matrix_sync(a, Qs + (wmS * 16) * 128 + kk, 128);
#pragma unroll
                for (int n = 0; n < 2; n++)
                    wmma::load_matrix_sync(bb[n], Ks + (wnS * 32 + n * 16) * 128 + kk, 128);
#pragma unroll
                for (int n = 0; n < 2; n++)
                    wmma::mma_sync(sacc[n], a, bb[n], sacc[n]);
            }
#pragma unroll
            for (int n = 0; n < 2; n++)
                wmma::store_matrix_sync(SP + (wmS * 16) * 68 + wnS * 32 + n * 16,
                                        sacc[n], 68, wmma::mem_row_major);
        }
        __syncthreads();

        // online softmax: 4 threads/row, 16 cols each
        {
            float* srow = SP + r_sm * 68 + sub * 16;
            int lim = q0 + r_sm - kbase - sub * 16;
            float mx = -INFINITY;
#pragma unroll
            for (int c = 0; c < 16; c++)
                if (c <= lim) mx = fmaxf(mx, srow[c]);
            mx = fmaxf(mx, __shfl_xor_sync(0xffffffffu, mx, 1));
            mx = fmaxf(mx, __shfl_xor_sync(0xffffffffu, mx, 2));
            float mnew = fmaxf(m_state, mx);
            float alpha = __expf(m_state - mnew);
            float sum = 0.f;
#pragma unroll
            for (int c = 0; c < 16; c++) {
                float p = (c <= lim) ? __expf(srow[c] - mnew) : 0.f;
                sum += p;
                srow[c] = to_tf32(p);
            }
            sum += __shfl_xor_sync(0xffffffffu, sum, 1);
            sum += __shfl_xor_sync(0xffffffffu, sum, 2);
            m_state = mnew;
            l_state = l_state * alpha + sum;
            if (sub == 0) arow[r_sm] = alpha;
        }
        __syncthreads();

        if (j + 1 < njt) {
            float* Vn = Vsm + (buf ^ 1) * 8192;
            const float4* Vg4 = (const float4*)(Vbase + (size_t)(j + 1) * 8192);
#pragma unroll
            for (int i = 0; i < 4; i++)
                cp_async16((float4*)Vn + tid + i * 512, Vg4 + tid + i * 512);
            CP_COMMIT;
            CP_WAIT2;
        } else {
            CP_WAIT0;
        }
        __syncthreads();

        // rescale O in registers, then O += P @ V  (warp: rows wmP*32, cols wnP*32)
        {
#pragma unroll
            for (int i = 0; i < 2; i++) {
                float al[8];
#pragma unroll
                for (int e = 0; e < 8; e++) al[e] = arow[wmP * 32 + i * 16 + rowmap[e]];
#pragma unroll
                for (int n = 0; n < 2; n++)
#pragma unroll
                    for (int e = 0; e < 8; e++) oacc[i][n].x[e] *= al[e];
            }
#pragma unroll
            for (int kk = 0; kk < 64; kk += 8) {
                wmma::fragment<wmma::matrix_a, 16, 16, 8, wmma::precision::tf32, wmma::row_major> a[2];
                wmma::fragment<wmma::matrix_b, 16, 16, 8, wmma::precision::tf32, wmma::row_major> bb[2];
#pragma unroll
                for (int i = 0; i < 2; i++)
                    wmma::load_matrix_sync(a[i], SP + (wmP * 32 + i * 16) * 68 + kk, 68);
#pragma unroll
                for (int n = 0; n < 2; n++)
                    wmma::load_matrix_sync(bb[n], Vs + kk * 128 + wnP * 32 + n * 16, 128);
#pragma unroll
                for (int i = 0; i < 2; i++)
#pragma unroll
                    for (int n = 0; n < 2; n++)
                        wmma::mma_sync(oacc[i][n], a[i], bb[n], oacc[i][n]);
            }
        }
    }

#pragma unroll
    for (int i = 0; i < 2; i++)
#pragma unroll
        for (int n = 0; n < 2; n++)
            wmma::store_matrix_sync(Osm + (wmP * 32 + i * 16) * 128 + wnP * 32 + n * 16,
                                    oacc[i][n], 128, wmma::mem_row_major);
    __syncthreads();
    if (sub == 0) arow[r_sm] = l_state;

    // stage per-position v rows into Qs
    {
        float* Vf = Qs;
        const float* vg = vlin + ((size_t)(b * T + q0)) * (KVH * HD) + kvh * HD;
        for (int i = tid; i < 128 * 32; i += 512) {
            int r = i >> 5, c = i & 31;
            ((float4*)(Vf + r * 128))[c] = ((const float4*)(vg + (size_t)r * (KVH * HD)))[c];
        }
    }
    __syncthreads();

    // epilogue: /l, v-orthogonalize, transpose-store (4 threads/row, 32 floats each)
    {
        const float* Vf = Qs;
        float invl = 1.0f / arow[r_sm];
        const float4* v4 = (const float4*)(Vf + r_sm * 128 + sub * 32);
        const float4* o4 = (const float4*)(Osm + r_sm * 128 + sub * 32);
        float sv2 = 0.f, dyv = 0.f;
#pragma unroll
        for (int cc = 0; cc < 8; cc++) {
            int c = (cc + r_sm) & 7;
            float4 vv = v4[c];
            float4 yy = o4[c];
            sv2 += vv.x * vv.x + vv.y * vv.y + vv.z * vv.z + vv.w * vv.w;
            dyv += yy.x * vv.x + yy.y * vv.y + yy.z * vv.z + yy.w * vv.w;
        }
        sv2 += __shfl_xor_sync(0xffffffffu, sv2, 1);
        sv2 += __shfl_xor_sync(0xffffffffu, sv2, 2);
        dyv += __shfl_xor_sync(0xffffffffu, dyv, 1);
        dyv += __shfl_xor_sync(0xffffffffu, dyv, 2);
        float nm = fmaxf(sqrtf(sv2), 1e-12f);
        float coef = (dyv * invl) / (nm * nm);
        float4* out4 = (float4*)(Y + (((size_t)(b * T + q0 + r_sm)) * H + h) * HD + sub * 32);
#pragma unroll
        for (int cc = 0; cc < 8; cc++) {
            int c = (cc + r_sm) & 7;
            float4 vv = v4[c];
            float4 yy = o4[c];
            float4 o;
            o.x = to_tf32(yy.x * invl - coef * vv.x);
            o.y = to_tf32(yy.y * invl - coef * vv.y);
            o.z = to_tf32(yy.z * invl - coef * vv.z);
            o.w = to_tf32(yy.w * invl - coef * vv.w);
            out4[c] = o;
        }
    }
}

// ---------------- launch -------------------------------------------------------
extern "C" void kernel_launch(void* const* d_in, const int* in_sizes, int n_in,
                              void* d_out, int out_size)
{
    const float* x    = (const float*)d_in[0];
    const float* Wq   = (const float*)d_in[1];
    const float* Wk   = (const float*)d_in[2];
    const float* Wv   = (const float*)d_in[3];
    const float* Wp   = (const float*)d_in[4];
    const float* gain = (const float*)d_in[5];

    float *qlin, *klin, *vlin, *q, *k, *v, *y;
    float *xt, *wqt, *wkt, *wvt, *wpt;
    cudaGetSymbolAddress((void**)&qlin, g_qlin);
    cudaGetSymbolAddress((void**)&klin, g_klin);
    cudaGetSymbolAddress((void**)&vlin, g_vlin);
    cudaGetSymbolAddress((void**)&q, g_q);
    cudaGetSymbolAddress((void**)&k, g_k);
    cudaGetSymbolAddress((void**)&v, g_v);
    cudaGetSymbolAddress((void**)&y, g_y);
    cudaGetSymbolAddress((void**)&xt, g_xt);
    cudaGetSymbolAddress((void**)&wqt, g_wqt);
    cudaGetSymbolAddress((void**)&wkt, g_wkt);
    cudaGetSymbolAddress((void**)&wvt, g_wvt);
    cudaGetSymbolAddress((void**)&wpt, g_wpt);

    cudaFuncSetAttribute(gemm_seg, cudaFuncAttributeMaxDynamicSharedMemorySize, GEMM_SMEM);
    cudaFuncSetAttribute(flash_kernel, cudaFuncAttributeMaxDynamicSharedMemorySize, FA_SMEM);

    // 0: fused tf32 truncation
    convert_all<<<(N4X + N4Q + N4K + N4V + N4P) / 256, 256>>>(
        x, Wq, Wk, Wv, Wp, xt, wqt, wkt, wvt, wpt);

    // 1: fused QKV projection (N = 2048 + 512 + 512)
    gemm_seg<<<dim3(24, MTOT / 128), 128, GEMM_SMEM>>>(
        xt, DIM,
        wqt, qlin, 16, DIM,
        wkt, klin, 4, KVH * HD,
        wvt, vlin, 4, KVH * HD);

    // 2: fused rms+rope (q,k) + v reorder
    rope_fused<<<(NWQ + NWK + NWV) / 4, 128>>>(qlin, klin, vlin, gain, q, k, v);

    // 3: flash attention + fused epilogue   (profiled launch)
    flash_kernel<<<dim3(T / 128, H, BATCH), 512, FA_SMEM>>>(q, k, v, vlin, y);

    // 4: output projection
    gemm_seg<<<dim3(16, MTOT / 128), 128, GEMM_SMEM>>>(
        y, DIM,
        wpt, (float*)d_out, 16, DIM,
        wpt, (float*)d_out, 0, DIM,
        wpt, (float*)d_out, 0, DIM);
}

// round 7
// speedup vs baseline: 4.2095x; 4.2095x over previous
#include <cuda_runtime.h>
#include <cuda_fp16.h>
#include <mma.h>
#include <math.h>
#include <cstdint>

using namespace nvcuda;

#define DIM 2048
#define H 16
#define KVH 4
#define HD 128
#define RD 64
#define BATCH 4
#define T 2048
#define MTOT (BATCH * T)   // 8192
#define SCALE 0.08838834764831845f
#define LOG2_10000 13.287712379549449f

// ---------------- scratch -----------------------------------------------------
__device__ float  g_qlin[MTOT * DIM];
__device__ float  g_klin[MTOT * KVH * HD];
__device__ float  g_vlin[MTOT * KVH * HD];
__device__ __half g_q[BATCH * H * T * HD];
__device__ __half g_k[BATCH * KVH * T * HD];
__device__ __half g_v[BATCH * KVH * T * HD];
__device__ __half g_y[MTOT * DIM];
__device__ __half g_xh[MTOT * DIM];
__device__ __half g_wqh[DIM * DIM];
__device__ __half g_wkh[KVH * HD * DIM];
__device__ __half g_wvh[KVH * HD * DIM];
__device__ __half g_wph[DIM * DIM];

// ---------------- helpers ------------------------------------------------------
__device__ __forceinline__ void cp_async16(void* smem, const void* gmem) {
    unsigned s = (unsigned)__cvta_generic_to_shared(smem);
    asm volatile("cp.async.cg.shared.global [%0], [%1], 16;\n" :: "r"(s), "l"(gmem) : "memory");
}
#define CP_COMMIT asm volatile("cp.async.commit_group;\n" ::: "memory")
#define CP_WAIT0  asm volatile("cp.async.wait_group 0;\n" ::: "memory")
#define CP_WAIT1  asm volatile("cp.async.wait_group 1;\n" ::: "memory")

// ---------------- fused fp16 conversion of all GEMM operands -------------------
#define N4X 4194304
#define N4Q 1048576
#define N4K 262144
#define N4V 262144
#define N4P 1048576
__global__ void convert_all(
    const float* __restrict__ x, const float* __restrict__ wq,
    const float* __restrict__ wk, const float* __restrict__ wv,
    const float* __restrict__ wp,
    __half* __restrict__ xh, __half* __restrict__ wqh,
    __half* __restrict__ wkh, __half* __restrict__ wvh, __half* __restrict__ wph)
{
    int i = blockIdx.x * blockDim.x + threadIdx.x;
    const float4* src; __half2* dst; int off;
    if (i < N4X)                         { src = (const float4*)x;  dst = (__half2*)xh;  off = 0; }
    else if (i < N4X + N4Q)              { src = (const float4*)wq; dst = (__half2*)wqh; off = N4X; }
    else if (i < N4X + N4Q + N4K)        { src = (const float4*)wk; dst = (__half2*)wkh; off = N4X + N4Q; }
    else if (i < N4X + N4Q + N4K + N4V)  { src = (const float4*)wv; dst = (__half2*)wvh; off = N4X + N4Q + N4K; }
    else                                 { src = (const float4*)wp; dst = (__half2*)wph; off = N4X + N4Q + N4K + N4V; }
    int j = i - off;
    float4 v = src[j];
    dst[j * 2]     = __floats2half2_rn(v.x, v.y);
    dst[j * 2 + 1] = __floats2half2_rn(v.z, v.w);
}

// ---------------- FP16 GEMM, segmented N ---------------------------------------
// C[M,n] = A[M,K] @ B[n,K]^T, fp16 in, fp32 out. BM=BN=128, BK=32, 4 warps
// (64x64 each), 3-stage cp.async, smem stride 40 halfs.
#define GSTR 40
#define GSTG (128 * GSTR)                 // halfs per matrix per stage
#define GEMM_SMEM (3 * 2 * GSTG * 2)      // 61440 bytes

__global__ void __launch_bounds__(128, 2) gemm_seg(
    const __half* __restrict__ A, int K,
    const __half* __restrict__ B0, float* __restrict__ C0, int t0, int ldc0,
    const __half* __restrict__ B1, float* __restrict__ C1, int t1, int ldc1,
    const __half* __restrict__ B2, float* __restrict__ C2, int t2, int ldc2)
{
    extern __shared__ __half hsm[];
    const int tid = threadIdx.x;
    const int warp = tid >> 5;
    const int wr = warp >> 1, wc = warp & 1;
    const int bm = blockIdx.y;
    int bn = blockIdx.x;

    const __half* B; float* C; int ldc;
    if (bn < t0)            { B = B0; C = C0; ldc = ldc0; }
    else if (bn < t0 + t1)  { B = B1; C = C1; ldc = ldc1; bn -= t0; }
    else                    { B = B2; C = C2; ldc = ldc2; bn -= t0 + t1; }

    const __half* Ab = A + (size_t)bm * 128 * K;
    const __half* Bb = B + (size_t)bn * 128 * K;

    wmma::fragment<wmma::accumulator, 16, 16, 16, float> acc[4][4];
#pragma unroll
    for (int i = 0; i < 4; i++)
#pragma unroll
        for (int j = 0; j < 4; j++) wmma::fill_fragment(acc[i][j], 0.0f);

    const int ntiles = K >> 5;
#pragma unroll
    for (int s = 0; s < 2; s++) {
        __half* As = hsm + s * 2 * GSTG;
        __half* Bs = As + GSTG;
#pragma unroll
        for (int i = 0; i < 4; i++) {
            int idx = tid + i * 128;           // 512 chunks of 16B per matrix
            int r = idx >> 2, c8 = (idx & 3) * 8;
            cp_async16(As + r * GSTR + c8, Ab + (size_t)r * K + s * 32 + c8);
            cp_async16(Bs + r * GSTR + c8, Bb + (size_t)r * K + s * 32 + c8);
        }
        CP_COMMIT;
    }

    for (int kt = 0; kt < ntiles; kt++) {
        CP_WAIT1;
        __syncthreads();
        __half* As = hsm + (kt % 3) * 2 * GSTG;
        __half* Bs = As + GSTG;
#pragma unroll
        for (int kk = 0; kk < 32; kk += 16) {
            wmma::fragment<wmma::matrix_a, 16, 16, 16, __half, wmma::row_major> a[4];
            wmma::fragment<wmma::matrix_b, 16, 16, 16, __half, wmma::col_major> bf[4];
#pragma unroll
            for (int i = 0; i < 4; i++)
                wmma::load_matrix_sync(a[i], As + (wr * 64 + i * 16) * GSTR + kk, GSTR);
#pragma unroll
            for (int j = 0; j < 4; j++)
                wmma::load_matrix_sync(bf[j], Bs + (wc * 64 + j * 16) * GSTR + kk, GSTR);
#pragma unroll
            for (int i = 0; i < 4; i++)
#pragma unroll
                for (int j = 0; j < 4; j++)
                    wmma::mma_sync(acc[i][j], a[i], bf[j], acc[i][j]);
        }
        __syncthreads();
        if (kt + 2 < ntiles) {
            int s = (kt + 2) % 3;
            int k0 = (kt + 2) * 32;
            __half* An = hsm + s * 2 * GSTG;
            __half* Bn = An + GSTG;
#pragma unroll
            for (int i = 0; i < 4; i++) {
                int idx = tid + i * 128;
                int r = idx >> 2, c8 = (idx & 3) * 8;
                cp_async16(An + r * GSTR + c8, Ab + (size_t)r * K + k0 + c8);
                cp_async16(Bn + r * GSTR + c8, Bb + (size_t)r * K + k0 + c8);
            }
        }
        CP_COMMIT;
    }

#pragma unroll
    for (int i = 0; i < 4; i++)
#pragma unroll
        for (int j = 0; j < 4; j++)
            wmma::store_matrix_sync(
                C + (size_t)(bm * 128 + wr * 64 + i * 16) * ldc + bn * 128 + wc * 64 + j * 16,
                acc[i][j], ldc, wmma::mem_row_major);
}

// ---------------- fused RMSNorm+RoPE (q,k) + v reorder, fp16 out ---------------
#define NWQ (BATCH * T * H)
#define NWK (BATCH * T * KVH)
#define NWV (BATCH * T * KVH)
__global__ void rope_fused(
    const float* __restrict__ qlin, const float* __restrict__ klin,
    const float* __restrict__ vlin, const float* __restrict__ gain,
    __half* __restrict__ qout, __half* __restrict__ kout, __half* __restrict__ vout)
{
    int w = (blockIdx.x * blockDim.x + threadIdx.x) >> 5;
    int lane = threadIdx.x & 31;

    if (w < NWQ + NWK) {
        bool isq = (w < NWQ);
        int hh, t, b, nh;
        const float* src;
        if (isq) {
            nh = H;
            hh = w % H; t = (w / H) % T; b = w / (H * T);
            src = qlin + ((size_t)(b * T + t)) * DIM + hh * HD;
        } else {
            int wk = w - NWQ;
            nh = KVH;
            hh = wk % KVH; t = (wk / KVH) % T; b = wk / (KVH * T);
            src = klin + ((size_t)(b * T + t)) * (KVH * HD) + hh * HD;
        }
        float v0 = src[lane], v1 = src[lane + 32], v2 = src[lane + 64], v3 = src[lane + 96];
        float ss = v0 * v0 + v1 * v1 + v2 * v2 + v3 * v3;
#pragma unroll
        for (int o = 16; o; o >>= 1) ss += __shfl_xor_sync(0xffffffffu, ss, o);
        float r = rsqrtf(ss * (1.0f / 128.0f) + 1e-6f);
        v0 *= r; v1 *= r; v2 *= r; v3 *= r;

        float inv = exp2f(-(float)lane * (LOG2_10000 / 32.0f));
        float fr = (float)t * inv;
        float sn, cs;
        sincosf(fr, &sn, &cs);
        float o0 = v0 * cs - v1 * sn;
        float o1 = v1 * cs + v0 * sn;

        float g = isq ? gain[hh] * SCALE : 1.0f;
        __half* dst = (isq ? qout : kout) + (((size_t)(b * nh + hh)) * T + t) * HD;
        dst[lane]      = __float2half_rn(o0 * g);
        dst[lane + 32] = __float2half_rn(o1 * g);
        dst[lane + 64] = __float2half_rn(v2 * g);
        dst[lane + 96] = __float2half_rn(v3 * g);
    } else {
        int u = w - NWQ - NWK;
        int kv = u & 3;
        int bt = u >> 2;
        int t = bt & (T - 1);
        int b = bt >> 11;
        float4 val = ((const float4*)vlin)[u * 32 + lane];
        __half2* dst = (__half2*)(vout + (((size_t)(b * KVH + kv)) * T + t) * HD);
        dst[lane * 2]     = __floats2half2_rn(val.x, val.y);
        dst[lane * 2 + 1] = __floats2half2_rn(val.z, val.w);
    }
}

// ---------------- Flash attention fp16 (BQ=128, BKV=64, 512 threads) -----------
// smem (bytes): Qh 0..34816 (128x136 h) | Ksm 34816..69632 (2x 64x136 h)
// | Vsm 69632..104448 | SP 104448..139264 (128x68 f) | Ph 139264..157696
// (128x72 h) | arow 157696..158208.  Osm (128x128 f, 64KB) reuses Qh+Ksm.
#define QSTR 136
#define SPSTR 68
#define PHSTR 72
#define FA_SMEM 158208

__global__ void __launch_bounds__(512) flash_kernel(
    const __half* __restrict__ Q, const __half* __restrict__ Kg,
    const __half* __restrict__ Vg, const float* __restrict__ vlin,
    __half* __restrict__ Y)
{
    extern __shared__ char sm[];
    __half* Qh  = (__half*)sm;
    __half* Ksm = (__half*)(sm + 34816);
    __half* Vsm = (__half*)(sm + 69632);
    float*  SP  = (float*)(sm + 104448);
    __half* Ph  = (__half*)(sm + 139264);
    float* arow = (float*)(sm + 157696);
    float*  Osm = (float*)sm;

    const int tid = threadIdx.x;
    const int warp = tid >> 5;                 // 0..15
    const int wmS = warp >> 1, wnS = warp & 1; // S: 16 rows x 32 cols
    const int wmP = warp >> 2, wnP = warp & 3; // PV: 32 rows x 32 cols
    const int qi = (gridDim.x - 1) - blockIdx.x;
    const int h = blockIdx.y, b = blockIdx.z;
    const int q0 = qi * 128;
    const int kvh = h >> 2;
    const int njt = 2 * qi + 2;

    const __half* Qbase = Q + (((size_t)b * H + h) * T + q0) * HD;
    const __half* Kbase = Kg + ((size_t)b * KVH + kvh) * T * HD;
    const __half* Vbase = Vg + ((size_t)b * KVH + kvh) * T * HD;

    // prologue: K0, V0 (64 rows x 16 chunks = 1024), Q (128 rows x 16 = 2048)
#pragma unroll
    for (int i = 0; i < 2; i++) {
        int idx = tid + i * 512;
        int r = idx >> 4, c = idx & 15;
        cp_async16((char*)Ksm + r * 272 + c * 16, Kbase + r * 128 + c * 8);
        cp_async16((char*)Vsm + r * 272 + c * 16, Vbase + r * 128 + c * 8);
    }
    CP_COMMIT;
#pragma unroll
    for (int i = 0; i < 4; i++) {
        int idx = tid + i * 512;
        int r = idx >> 4, c = idx & 15;
        cp_async16((char*)Qh + r * 272 + c * 16, Qbase + r * 128 + c * 8);
    }
    CP_COMMIT;
    if (tid < 256) {
        int r = tid >> 4, c = tid & 15;
        SP[r * SPSTR + c] = (float)r;
    }
    CP_WAIT0;
    __syncthreads();

    // accumulator row map + loop-invariant Q fragments (8 k-steps)
    int rowmap[8];
    {
        wmma::fragment<wmma::accumulator, 16, 16, 16, float> probe;
        wmma::load_matrix_sync(probe, SP, SPSTR, wmma::mem_row_major);
#pragma unroll
        for (int e = 0; e < 8; e++) rowmap[e] = (int)probe.x[e];
    }
    wmma::fragment<wmma::matrix_a, 16, 16, 16, __half, wmma::row_major> qfrag[8];
#pragma unroll
    for (int kk = 0; kk < 8; kk++)
        wmma::load_matrix_sync(qfrag[kk], Qh + (wmS * 16) * QSTR + kk * 16, QSTR);

    wmma::fragment<wmma::accumulator, 16, 16, 16, float> oacc[2][2];
#pragma unroll
    for (int i = 0; i < 2; i++)
#pragma unroll
        for (int n = 0; n < 2; n++) wmma::fill_fragment(oacc[i][n], 0.0f);

    const int r_sm = tid >> 2, sub = tid & 3;   // softmax: 4 threads/row
    float m_state = -INFINITY, l_state = 0.f;

    for (int j = 0; j < njt; j++) {
        const int buf = j & 1;
        __half* Ks = Ksm + buf * 8704;   // 64*136
        __half* Vs = Vsm + buf * 8704;
        const int kbase = j * 64;

        // prefetch next K+V into other buffer (consumed next iter)
        if (j + 1 < njt) {
            __half* Kn = Ksm + (buf ^ 1) * 8704;
            __half* Vn = Vsm + (buf ^ 1) * 8704;
            const __half* Kg4 = Kbase + (size_t)(j + 1) * 8192;
            const __half* Vg4 = Vbase + (size_t)(j + 1) * 8192;
#pragma unroll
            for (int i = 0; i < 2; i++) {
                int idx = tid + i * 512;
                int r = idx >> 4, c = idx & 15;
                cp_async16((char*)Kn + r * 272 + c * 16, Kg4 + r * 128 + c * 8);
                cp_async16((char*)Vn + r * 272 + c * 16, Vg4 + r * 128 + c * 8);
            }
            CP_COMMIT;
        }

        // S = Q @ K^T : warp -> rows [wmS*16), cols [wnS*32)
        {
            wmma::fragment<wmma::accumulator, 16, 16, 16, float> sacc[2];
            wmma::fill_fragment(sacc[0], 0.0f);
            wmma::fill_fragment(sacc[1], 0.0f);
#pragma unroll
            for (int kk = 0; kk < 8; kk++) {
                wmma::fragment<wmma::matrix_b, 16, 16, 16, __half, wmma::col_major> bb[2];
#pragma unroll
                for (int n = 0; n < 2; n++)
                    wmma::load_matrix_sync(bb[n], Ks + (wnS * 32 + n * 16) * QSTR + kk * 16, QSTR);
#pragma unroll
                for (int n = 0; n < 2; n++)
                    wmma::mma_sync(sacc[n], qfrag[kk], bb[n], sacc[n]);
            }
#pragma unroll
            for (int n = 0; n < 2; n++)
                wmma::store_matrix_sync(SP + (wmS * 16) * SPSTR + wnS * 32 + n * 16,
                                        sacc[n], SPSTR, wmma::mem_row_major);
        }
        __syncthreads();

        // online softmax: 4 threads/row, 16 cols each; write P to fp16
        {
            float* srow = SP + r_sm * SPSTR + sub * 16;
            __half* prow = Ph + r_sm * PHSTR + sub * 16;
            int lim = q0 + r_sm - kbase - sub * 16;
            float mx = -INFINITY;
#pragma unroll
            for (int c = 0; c < 16; c++)
                if (c <= lim) mx = fmaxf(mx, srow[c]);
            mx = fmaxf(mx, __shfl_xor_sync(0xffffffffu, mx, 1));
            mx = fmaxf(mx, __shfl_xor_sync(0xffffffffu, mx, 2));
            float mnew = fmaxf(m_state, mx);
            float alpha = __expf(m_state - mnew);
            float sum = 0.f;
#pragma unroll
            for (int c = 0; c < 16; c++) {
                float p = (c <= lim) ? __expf(srow[c] - mnew) : 0.f;
                sum += p;
                prow[c] = __float2half_rn(p);
            }
            sum += __shfl_xor_sync(0xffffffffu, sum, 1);
            sum += __shfl_xor_sync(0xffffffffu, sum, 2);
            m_state = mnew;
            l_state = l_state * alpha + sum;
            if (sub == 0) arow[r_sm] = alpha;
        }
        __syncthreads();

        // rescale O in registers, then O += P @ V (warp: rows wmP*32, cols wnP*32)
        {
#pragma unroll
            for (int i = 0; i < 2; i++) {
                float al[8];
#pragma unroll
                for (int e = 0; e < 8; e++) al[e] = arow[wmP * 32 + i * 16 + rowmap[e]];
#pragma unroll
                for (int n = 0; n < 2; n++)
#pragma unroll
                    for (int e = 0; e < 8; e++) oacc[i][n].x[e] *= al[e];
            }
#pragma unroll
            for (int kk = 0; kk < 4; kk++) {
                wmma::fragment<wmma::matrix_a, 16, 16, 16, __half, wmma::row_major> a[2];
                wmma::fragment<wmma::matrix_b, 16, 16, 16, __half, wmma::row_major> bb[2];
#pragma unroll
                for (int i = 0; i < 2; i++)
                    wmma::load_matrix_sync(a[i], Ph + (wmP * 32 + i * 16) * PHSTR + kk * 16, PHSTR);
#pragma unroll
                for (int n = 0; n < 2; n++)
                    wmma::load_matrix_sync(bb[n], Vs + (kk * 16) * QSTR + wnP * 32 + n * 16, QSTR);
#pragma unroll
                for (int i = 0; i < 2; i++)
#pragma unroll
                    for (int n = 0; n < 2; n++)
                        wmma::mma_sync(oacc[i][n], a[i], bb[n], oacc[i][n]);
            }
        }
        // wait for next K/V; sync also protects SP/Ph/arow reuse
        if (j + 1 < njt) CP_WAIT0;
        __syncthreads();
    }

    // store O (fp32) over Qh/Ksm region
#pragma unroll
    for (int i = 0; i < 2; i++)
#pragma unroll
        for (int n = 0; n < 2; n++)
            wmma::store_matrix_sync(Osm + (wmP * 32 + i * 16) * 128 + wnP * 32 + n * 16,
                                    oacc[i][n], 128, wmma::mem_row_major);
    if (sub == 0) arow[r_sm] = l_state;
    __syncthreads();

    // epilogue: /l, v-orthogonalize (fp32 v from gmem), store y fp16
    {
        float invl = 1.0f / arow[r_sm];
        const float4* v4 = (const float4*)(vlin + ((size_t)(b * T + q0 + r_sm)) * (KVH * HD)
                                           + kvh * HD + sub * 32);
        const float4* o4 = (const float4*)(Osm + r_sm * 128 + sub * 32);
        float4 vv[8], yy[8];
        float sv2 = 0.f, dyv = 0.f;
#pragma unroll
        for (int c = 0; c < 8; c++) {
            vv[c] = v4[c];
            yy[c] = o4[(c + r_sm) & 7];   // bank-staggered smem read
        }
#pragma unroll
        for (int c = 0; c < 8; c++) {
            int cc = (c + r_sm) & 7;       // align yy index back to column
            float4 t = vv[cc];
            sv2 += t.x * t.x + t.y * t.y + t.z * t.z + t.w * t.w;
            dyv += yy[c].x * t.x + yy[c].y * t.y + yy[c].z * t.z + yy[c].w * t.w;
        }
        sv2 += __shfl_xor_sync(0xffffffffu, sv2, 1);
        sv2 += __shfl_xor_sync(0xffffffffu, sv2, 2);
        dyv += __shfl_xor_sync(0xffffffffu, dyv, 1);
        dyv += __shfl_xor_sync(0xffffffffu, dyv, 2);
        float nm = fmaxf(sqrtf(sv2), 1e-12f);
        float coef = (dyv * invl) / (nm * nm);
        __half2* out2 = (__half2*)(Y + (((size_t)(b * T + q0 + r_sm)) * H + h) * HD + sub * 32);
#pragma unroll
        for (int c = 0; c < 8; c++) {
            int cc = (c + r_sm) & 7;
            float4 t = vv[cc];
            float4 y4 = yy[c];
            out2[cc * 2]     = __floats2half2_rn(y4.x * invl - coef * t.x,
                                                 y4.y * invl - coef * t.y);
            out2[cc * 2 + 1] = __floats2half2_rn(y4.z * invl - coef * t.z,
                                                 y4.w * invl - coef * t.w);
        }
    }
}

// ---------------- launch -------------------------------------------------------
extern "C" void kernel_launch(void* const* d_in, const int* in_sizes, int n_in,
                              void* d_out, int out_size)
{
    const float* x    = (const float*)d_in[0];
    const float* Wq   = (const float*)d_in[1];
    const float* Wk   = (const float*)d_in[2];
    const float* Wv   = (const float*)d_in[3];
    const float* Wp   = (const float*)d_in[4];
    const float* gain = (const float*)d_in[5];

    float *qlin, *klin, *vlin;
    __half *q, *k, *v, *y, *xh, *wqh, *wkh, *wvh, *wph;
    cudaGetSymbolAddress((void**)&qlin, g_qlin);
    cudaGetSymbolAddress((void**)&klin, g_klin);
    cudaGetSymbolAddress((void**)&vlin, g_vlin);
    cudaGetSymbolAddress((void**)&q, g_q);
    cudaGetSymbolAddress((void**)&k, g_k);
    cudaGetSymbolAddress((void**)&v, g_v);
    cudaGetSymbolAddress((void**)&y, g_y);
    cudaGetSymbolAddress((void**)&xh, g_xh);
    cudaGetSymbolAddress((void**)&wqh, g_wqh);
    cudaGetSymbolAddress((void**)&wkh, g_wkh);
    cudaGetSymbolAddress((void**)&wvh, g_wvh);
    cudaGetSymbolAddress((void**)&wph, g_wph);

    cudaFuncSetAttribute(gemm_seg, cudaFuncAttributeMaxDynamicSharedMemorySize, GEMM_SMEM);
    cudaFuncSetAttribute(flash_kernel, cudaFuncAttributeMaxDynamicSharedMemorySize, FA_SMEM);

    // 0: fused fp16 conversion
    convert_all<<<(N4X + N4Q + N4K + N4V + N4P) / 256, 256>>>(
        x, Wq, Wk, Wv, Wp, xh, wqh, wkh, wvh, wph);

    // 1: fused QKV projection (N = 2048 + 512 + 512)
    gemm_seg<<<dim3(24, MTOT / 128), 128, GEMM_SMEM>>>(
        xh, DIM,
        wqh, qlin, 16, DIM,
        wkh, klin, 4, KVH * HD,
        wvh, vlin, 4, KVH * HD);

    // 2: fused rms+rope (q,k) + v reorder -> fp16
    rope_fused<<<(NWQ + NWK + NWV) / 4, 128>>>(qlin, klin, vlin, gain, q, k, v);

    // 3: flash attention fp16 + fused epilogue   (profiled launch)
    flash_kernel<<<dim3(T / 128, H, BATCH), 512, FA_SMEM>>>(q, k, v, vlin, y);

    // 4: output projection (y fp16 -> d_out fp32)
    gemm_seg<<<dim3(16, MTOT / 128), 128, GEMM_SMEM>>>(
        y, DIM,
        wph, (float*)d_out, 16, DIM,
        wph, (float*)d_out, 0, DIM,
        wph, (float*)d_out, 0, DIM);
}

// round 8
// speedup vs baseline: 5.5201x; 1.3113x over previous
#include <cuda_runtime.h>
#include <cuda_fp16.h>
#include <mma.h>
#include <math.h>
#include <cstdint>

using namespace nvcuda;

#define DIM 2048
#define H 16
#define KVH 4
#define HD 128
#define RD 64
#define BATCH 4
#define T 2048
#define MTOT (BATCH * T)   // 8192
#define SCALE 0.08838834764831845f
#define LOG2_10000 13.287712379549449f

// ---------------- scratch -----------------------------------------------------
__device__ float  g_qlin[MTOT * DIM];
__device__ float  g_klin[MTOT * KVH * HD];
__device__ float  g_vlin[MTOT * KVH * HD];
__device__ __half g_q[BATCH * H * T * HD];
__device__ __half g_k[BATCH * KVH * T * HD];
__device__ __half g_v[BATCH * KVH * T * HD];
__device__ __half g_y[MTOT * DIM];
__device__ __half g_xh[MTOT * DIM];
__device__ __half g_wqh[DIM * DIM];
__device__ __half g_wkh[KVH * HD * DIM];
__device__ __half g_wvh[KVH * HD * DIM];
__device__ __half g_wph[DIM * DIM];

// ---------------- helpers ------------------------------------------------------
__device__ __forceinline__ void cp_async16(void* smem, const void* gmem) {
    unsigned s = (unsigned)__cvta_generic_to_shared(smem);
    asm volatile("cp.async.cg.shared.global [%0], [%1], 16;\n" :: "r"(s), "l"(gmem) : "memory");
}
#define CP_COMMIT asm volatile("cp.async.commit_group;\n" ::: "memory")
#define CP_WAIT0  asm volatile("cp.async.wait_group 0;\n" ::: "memory")
#define CP_WAIT1  asm volatile("cp.async.wait_group 1;\n" ::: "memory")

__device__ __forceinline__ void ldm_x4(uint32_t a, uint32_t& r0, uint32_t& r1,
                                       uint32_t& r2, uint32_t& r3) {
    asm volatile("ldmatrix.sync.aligned.m8n8.x4.shared.b16 {%0,%1,%2,%3}, [%4];"
                 : "=r"(r0), "=r"(r1), "=r"(r2), "=r"(r3) : "r"(a));
}
__device__ __forceinline__ void ldm_x4_t(uint32_t a, uint32_t& r0, uint32_t& r1,
                                         uint32_t& r2, uint32_t& r3) {
    asm volatile("ldmatrix.sync.aligned.m8n8.x4.trans.shared.b16 {%0,%1,%2,%3}, [%4];"
                 : "=r"(r0), "=r"(r1), "=r"(r2), "=r"(r3) : "r"(a));
}
__device__ __forceinline__ void mma16816(float* c, const uint32_t* a, const uint32_t* b) {
    asm volatile("mma.sync.aligned.m16n8k16.row.col.f32.f16.f16.f32 "
                 "{%0,%1,%2,%3}, {%4,%5,%6,%7}, {%8,%9}, {%0,%1,%2,%3};"
                 : "+f"(c[0]), "+f"(c[1]), "+f"(c[2]), "+f"(c[3])
                 : "r"(a[0]), "r"(a[1]), "r"(a[2]), "r"(a[3]), "r"(b[0]), "r"(b[1]));
}
__device__ __forceinline__ uint32_t h2pack(float x, float y) {
    __half2 h = __floats2half2_rn(x, y);
    return *(uint32_t*)&h;
}

// ---------------- fused fp16 conversion of all GEMM operands -------------------
#define N4X 4194304
#define N4Q 1048576
#define N4K 262144
#define N4V 262144
#define N4P 1048576
__global__ void convert_all(
    const float* __restrict__ x, const float* __restrict__ wq,
    const float* __restrict__ wk, const float* __restrict__ wv,
    const float* __restrict__ wp,
    __half* __restrict__ xh, __half* __restrict__ wqh,
    __half* __restrict__ wkh, __half* __restrict__ wvh, __half* __restrict__ wph)
{
    int i = blockIdx.x * blockDim.x + threadIdx.x;
    const float4* src; __half2* dst; int off;
    if (i < N4X)                         { src = (const float4*)x;  dst = (__half2*)xh;  off = 0; }
    else if (i < N4X + N4Q)              { src = (const float4*)wq; dst = (__half2*)wqh; off = N4X; }
    else if (i < N4X + N4Q + N4K)        { src = (const float4*)wk; dst = (__half2*)wkh; off = N4X + N4Q; }
    else if (i < N4X + N4Q + N4K + N4V)  { src = (const float4*)wv; dst = (__half2*)wvh; off = N4X + N4Q + N4K; }
    else                                 { src = (const float4*)wp; dst = (__half2*)wph; off = N4X + N4Q + N4K + N4V; }
    int j = i - off;
    float4 v = src[j];
    dst[j * 2]     = __floats2half2_rn(v.x, v.y);
    dst[j * 2 + 1] = __floats2half2_rn(v.z, v.w);
}

// ---------------- FP16 GEMM, segmented N ---------------------------------------
#define GSTR 40
#define GSTG (128 * GSTR)
#define GEMM_SMEM (3 * 2 * GSTG * 2)      // 61440 bytes

__global__ void __launch_bounds__(128, 2) gemm_seg(
    const __half* __restrict__ A, int K,
    const __half* __restrict__ B0, float* __restrict__ C0, int t0, int ldc0,
    const __half* __restrict__ B1, float* __restrict__ C1, int t1, int ldc1,
    const __half* __restrict__ B2, float* __restrict__ C2, int t2, int ldc2)
{
    extern __shared__ __half hsm[];
    const int tid = threadIdx.x;
    const int warp = tid >> 5;
    const int wr = warp >> 1, wc = warp & 1;
    const int bm = blockIdx.y;
    int bn = blockIdx.x;

    const __half* B; float* C; int ldc;
    if (bn < t0)            { B = B0; C = C0; ldc = ldc0; }
    else if (bn < t0 + t1)  { B = B1; C = C1; ldc = ldc1; bn -= t0; }
    else                    { B = B2; C = C2; ldc = ldc2; bn -= t0 + t1; }

    const __half* Ab = A + (size_t)bm * 128 * K;
    const __half* Bb = B + (size_t)bn * 128 * K;

    wmma::fragment<wmma::accumulator, 16, 16, 16, float> acc[4][4];
#pragma unroll
    for (int i = 0; i < 4; i++)
#pragma unroll
        for (int j = 0; j < 4; j++) wmma::fill_fragment(acc[i][j], 0.0f);

    const int ntiles = K >> 5;
#pragma unroll
    for (int s = 0; s < 2; s++) {
        __half* As = hsm + s * 2 * GSTG;
        __half* Bs = As + GSTG;
#pragma unroll
        for (int i = 0; i < 4; i++) {
            int idx = tid + i * 128;
            int r = idx >> 2, c8 = (idx & 3) * 8;
            cp_async16(As + r * GSTR + c8, Ab + (size_t)r * K + s * 32 + c8);
            cp_async16(Bs + r * GSTR + c8, Bb + (size_t)r * K + s * 32 + c8);
        }
        CP_COMMIT;
    }

    for (int kt = 0; kt < ntiles; kt++) {
        CP_WAIT1;
        __syncthreads();
        __half* As = hsm + (kt % 3) * 2 * GSTG;
        __half* Bs = As + GSTG;
#pragma unroll
        for (int kk = 0; kk < 32; kk += 16) {
            wmma::fragment<wmma::matrix_a, 16, 16, 16, __half, wmma::row_major> a[4];
            wmma::fragment<wmma::matrix_b, 16, 16, 16, __half, wmma::col_major> bf[4];
#pragma unroll
            for (int i = 0; i < 4; i++)
                wmma::load_matrix_sync(a[i], As + (wr * 64 + i * 16) * GSTR + kk, GSTR);
#pragma unroll
            for (int j = 0; j < 4; j++)
                wmma::load_matrix_sync(bf[j], Bs + (wc * 64 + j * 16) * GSTR + kk, GSTR);
#pragma unroll
            for (int i = 0; i < 4; i++)
#pragma unroll
                for (int j = 0; j < 4; j++)
                    wmma::mma_sync(acc[i][j], a[i], bf[j], acc[i][j]);
        }
        __syncthreads();
        if (kt + 2 < ntiles) {
            int s = (kt + 2) % 3;
            int k0 = (kt + 2) * 32;
            __half* An = hsm + s * 2 * GSTG;
            __half* Bn = An + GSTG;
#pragma unroll
            for (int i = 0; i < 4; i++) {
                int idx = tid + i * 128;
                int r = idx >> 2, c8 = (idx & 3) * 8;
                cp_async16(An + r * GSTR + c8, Ab + (size_t)r * K + k0 + c8);
                cp_async16(Bn + r * GSTR + c8, Bb + (size_t)r * K + k0 + c8);
            }
        }
        CP_COMMIT;
    }

#pragma unroll
    for (int i = 0; i < 4; i++)
#pragma unroll
        for (int j = 0; j < 4; j++)
            wmma::store_matrix_sync(
                C + (size_t)(bm * 128 + wr * 64 + i * 16) * ldc + bn * 128 + wc * 64 + j * 16,
                acc[i][j], ldc, wmma::mem_row_major);
}

// ---------------- fused RMSNorm+RoPE (q,k) + v reorder, fp16 out ---------------
#define NWQ (BATCH * T * H)
#define NWK (BATCH * T * KVH)
#define NWV (BATCH * T * KVH)
__global__ void rope_fused(
    const float* __restrict__ qlin, const float* __restrict__ klin,
    const float* __restrict__ vlin, const float* __restrict__ gain,
    __half* __restrict__ qout, __half* __restrict__ kout, __half* __restrict__ vout)
{
    int w = (blockIdx.x * blockDim.x + threadIdx.x) >> 5;
    int lane = threadIdx.x & 31;

    if (w < NWQ + NWK) {
        bool isq = (w < NWQ);
        int hh, t, b, nh;
        const float* src;
        if (isq) {
            nh = H;
            hh = w % H; t = (w / H) % T; b = w / (H * T);
            src = qlin + ((size_t)(b * T + t)) * DIM + hh * HD;
        } else {
            int wk = w - NWQ;
            nh = KVH;
            hh = wk % KVH; t = (wk / KVH) % T; b = wk / (KVH * T);
            src = klin + ((size_t)(b * T + t)) * (KVH * HD) + hh * HD;
        }
        float v0 = src[lane], v1 = src[lane + 32], v2 = src[lane + 64], v3 = src[lane + 96];
        float ss = v0 * v0 + v1 * v1 + v2 * v2 + v3 * v3;
#pragma unroll
        for (int o = 16; o; o >>= 1) ss += __shfl_xor_sync(0xffffffffu, ss, o);
        float r = rsqrtf(ss * (1.0f / 128.0f) + 1e-6f);
        v0 *= r; v1 *= r; v2 *= r; v3 *= r;

        float inv = exp2f(-(float)lane * (LOG2_10000 / 32.0f));
        float fr = (float)t * inv;
        float sn, cs;
        sincosf(fr, &sn, &cs);
        float o0 = v0 * cs - v1 * sn;
        float o1 = v1 * cs + v0 * sn;

        float g = isq ? gain[hh] * SCALE : 1.0f;
        __half* dst = (isq ? qout : kout) + (((size_t)(b * nh + hh)) * T + t) * HD;
        dst[lane]      = __float2half_rn(o0 * g);
        dst[lane + 32] = __float2half_rn(o1 * g);
        dst[lane + 64] = __float2half_rn(v2 * g);
        dst[lane + 96] = __float2half_rn(v3 * g);
    } else {
        int u = w - NWQ - NWK;
        int kv = u & 3;
        int bt = u >> 2;
        int t = bt & (T - 1);
        int b = bt >> 11;
        float4 val = ((const float4*)vlin)[u * 32 + lane];
        __half2* dst = (__half2*)(vout + (((size_t)(b * KVH + kv)) * T + t) * HD);
        dst[lane * 2]     = __floats2half2_rn(val.x, val.y);
        dst[lane * 2 + 1] = __floats2half2_rn(val.z, val.w);
    }
}

// ---------------- Flash attention FA2-style (BQ=128, BKV=64, 256 thr) ----------
// smem (bytes): Qh 0..34816 (128x136 h) | Ks 34816 (2 x 64x136 h = 2x17408)
// | Vs 69632 (2 x 17408).  Total 104448.
#define QSTR 136
#define FA_SMEM 104448

__global__ void __launch_bounds__(256) flash_kernel(
    const __half* __restrict__ Q, const __half* __restrict__ Kg,
    const __half* __restrict__ Vg, const float* __restrict__ vlin,
    __half* __restrict__ Y)
{
    extern __shared__ char sm[];
    const uint32_t smem_base = (uint32_t)__cvta_generic_to_shared(sm);
    const uint32_t Ks_base = smem_base + 34816;
    const uint32_t Vs_base = smem_base + 69632;

    const int tid = threadIdx.x;
    const int warp = tid >> 5;      // 0..7, owns q rows [warp*16, +16)
    const int lane = tid & 31;
    const int qi = (gridDim.x - 1) - blockIdx.x;
    const int h = blockIdx.y, b = blockIdx.z;
    const int q0 = qi * 128;
    const int kvh = h >> 2;
    const int njt = 2 * qi + 2;

    const __half* Qbase = Q + (((size_t)b * H + h) * T + q0) * HD;
    const __half* Kbase = Kg + ((size_t)b * KVH + kvh) * T * HD;
    const __half* Vbase = Vg + ((size_t)b * KVH + kvh) * T * HD;

    // prologue: K0 + V0 (64 rows x 16 chunks each), Q (128 rows x 16 chunks)
#pragma unroll
    for (int i = 0; i < 4; i++) {
        int idx = tid + i * 256;
        int r = idx >> 4, c = idx & 15;
        cp_async16(sm + 34816 + r * 272 + c * 16, Kbase + r * 128 + c * 8);
        cp_async16(sm + 69632 + r * 272 + c * 16, Vbase + r * 128 + c * 8);
    }
    CP_COMMIT;
#pragma unroll
    for (int i = 0; i < 8; i++) {
        int idx = tid + i * 256;
        int r = idx >> 4, c = idx & 15;
        cp_async16(sm + r * 272 + c * 16, Qbase + r * 128 + c * 8);
    }
    CP_COMMIT;
    CP_WAIT0;
    __syncthreads();

    // Q fragments: 8 kk-steps, loop-invariant
    uint32_t qf[8][4];
    {
        uint32_t qaddr = smem_base +
            ((uint32_t)(warp * 16 + (lane & 15)) * QSTR + (uint32_t)(lane >> 4) * 8) * 2;
#pragma unroll
        for (int kk = 0; kk < 8; kk++)
            ldm_x4(qaddr + kk * 32, qf[kk][0], qf[kk][1], qf[kk][2], qf[kk][3]);
    }

    // lane-constant ldmatrix offsets (in halfs)
    const int g8 = lane >> 3, l8 = lane & 7;
    const uint32_t laneK = (uint32_t)(((g8 >= 2) ? 8 : 0) + l8) * QSTR + ((g8 & 1) ? 8 : 0);
    const uint32_t laneVr = (uint32_t)((g8 & 1) * 8 + l8);
    const uint32_t laneVc = (g8 >= 2) ? 8 : 0;

    const int rowA = q0 + warp * 16 + (lane >> 2);   // global q row for c0/c1
    const int colb = (lane & 3) * 2;                 // column base within an 8-wide ntile

    float oacc[16][4];
#pragma unroll
    for (int nt = 0; nt < 16; nt++)
#pragma unroll
        for (int e = 0; e < 4; e++) oacc[nt][e] = 0.f;
    float mA = -1e30f, mB = -1e30f, lA = 0.f, lB = 0.f;

    for (int j = 0; j < njt; j++) {
        const int buf = j & 1;
        const uint32_t Ks = Ks_base + buf * 17408;
        const uint32_t Vs = Vs_base + buf * 17408;
        const int kbase = j * 64;

        if (j + 1 < njt) {
            const __half* Kn = Kbase + (size_t)(j + 1) * 8192;
            const __half* Vn = Vbase + (size_t)(j + 1) * 8192;
            char* Kd = sm + 34816 + (buf ^ 1) * 17408;
            char* Vd = sm + 69632 + (buf ^ 1) * 17408;
#pragma unroll
            for (int i = 0; i < 4; i++) {
                int idx = tid + i * 256;
                int r = idx >> 4, c = idx & 15;
                cp_async16(Kd + r * 272 + c * 16, Kn + r * 128 + c * 8);
                cp_async16(Vd + r * 272 + c * 16, Vn + r * 128 + c * 8);
            }
            CP_COMMIT;
        }

        // ---- S = Q K^T : 8 ntiles (8 kv cols each) in registers ----
        float sacc[8][4];
#pragma unroll
        for (int nt = 0; nt < 8; nt++)
#pragma unroll
            for (int e = 0; e < 4; e++) sacc[nt][e] = 0.f;
#pragma unroll
        for (int kk = 0; kk < 8; kk++) {
#pragma unroll
            for (int p = 0; p < 4; p++) {
                uint32_t b0, b1, b2, b3;
                ldm_x4(Ks + ((uint32_t)(p * 16) * QSTR + (uint32_t)(kk * 16) + laneK) * 2,
                       b0, b1, b2, b3);
                uint32_t bb0[2] = {b0, b1}, bb1[2] = {b2, b3};
                mma16816(sacc[2 * p],     qf[kk], bb0);
                mma16816(sacc[2 * p + 1], qf[kk], bb1);
            }
        }

        // ---- causal mask (diagonal tiles only) ----
        if (kbase + 63 > rowA) {
            int limA = rowA - kbase;
#pragma unroll
            for (int nt = 0; nt < 8; nt++) {
                int c0 = nt * 8 + colb;
                if (c0 > limA)     sacc[nt][0] = -1e30f;
                if (c0 + 1 > limA) sacc[nt][1] = -1e30f;
                if (c0 > limA + 8)     sacc[nt][2] = -1e30f;
                if (c0 + 1 > limA + 8) sacc[nt][3] = -1e30f;
            }
        }

        // ---- online softmax, fully in registers ----
        float mxA = -1e30f, mxB = -1e30f;
#pragma unroll
        for (int nt = 0; nt < 8; nt++) {
            mxA = fmaxf(mxA, fmaxf(sacc[nt][0], sacc[nt][1]));
            mxB = fmaxf(mxB, fmaxf(sacc[nt][2], sacc[nt][3]));
        }
        mxA = fmaxf(mxA, __shfl_xor_sync(0xffffffffu, mxA, 1));
        mxA = fmaxf(mxA, __shfl_xor_sync(0xffffffffu, mxA, 2));
        mxB = fmaxf(mxB, __shfl_xor_sync(0xffffffffu, mxB, 1));
        mxB = fmaxf(mxB, __shfl_xor_sync(0xffffffffu, mxB, 2));
        float mnA = fmaxf(mA, mxA), mnB = fmaxf(mB, mxB);
        float aA = __expf(mA - mnA), aB = __expf(mB - mnB);

        uint32_t pa[4][4];
        float sA = 0.f, sB = 0.f;
#pragma unroll
        for (int k2 = 0; k2 < 4; k2++) {
            float p00 = __expf(sacc[2 * k2][0] - mnA);
            float p01 = __expf(sacc[2 * k2][1] - mnA);
            float p10 = __expf(sacc[2 * k2][2] - mnB);
            float p11 = __expf(sacc[2 * k2][3] - mnB);
            float p20 = __expf(sacc[2 * k2 + 1][0] - mnA);
            float p21 = __expf(sacc[2 * k2 + 1][1] - mnA);
            float p30 = __expf(sacc[2 * k2 + 1][2] - mnB);
            float p31 = __expf(sacc[2 * k2 + 1][3] - mnB);
            sA += p00 + p01 + p20 + p21;
            sB += p10 + p11 + p30 + p31;
            pa[k2][0] = h2pack(p00, p01);
            pa[k2][1] = h2pack(p10, p11);
            pa[k2][2] = h2pack(p20, p21);
            pa[k2][3] = h2pack(p30, p31);
        }
        sA += __shfl_xor_sync(0xffffffffu, sA, 1);
        sA += __shfl_xor_sync(0xffffffffu, sA, 2);
        sB += __shfl_xor_sync(0xffffffffu, sB, 1);
        sB += __shfl_xor_sync(0xffffffffu, sB, 2);
        lA = lA * aA + sA;
        lB = lB * aB + sB;
        mA = mnA; mB = mnB;

        // rescale O
#pragma unroll
        for (int nt = 0; nt < 16; nt++) {
            oacc[nt][0] *= aA; oacc[nt][1] *= aA;
            oacc[nt][2] *= aB; oacc[nt][3] *= aB;
        }

        // ---- O += P V ----
#pragma unroll
        for (int k2 = 0; k2 < 4; k2++) {
#pragma unroll
            for (int p = 0; p < 8; p++) {
                uint32_t v0, v1, v2, v3;
                ldm_x4_t(Vs + (((uint32_t)(k2 * 16) + laneVr) * QSTR
                               + (uint32_t)(p * 16) + laneVc) * 2,
                         v0, v1, v2, v3);
                uint32_t vb0[2] = {v0, v1}, vb1[2] = {v2, v3};
                mma16816(oacc[2 * p],     pa[k2], vb0);
                mma16816(oacc[2 * p + 1], pa[k2], vb1);
            }
        }

        if (j + 1 < njt) CP_WAIT0;
        __syncthreads();
    }

    // ---- epilogue: /l, v-orthogonalize (fp32 v from gmem), store fp16 ----
    {
        float invlA = 1.f / lA, invlB = 1.f / lB;
        const float* vAp = vlin + ((size_t)(b * T) + rowA) * (KVH * HD) + kvh * HD + colb;
        const float* vBp = vAp + (size_t)8 * (KVH * HD);
        float svA = 0.f, dyA = 0.f, svB = 0.f, dyB = 0.f;
#pragma unroll
        for (int nt = 0; nt < 16; nt++) {
            float2 va = *(const float2*)(vAp + nt * 8);
            float2 vb2 = *(const float2*)(vBp + nt * 8);
            svA += va.x * va.x + va.y * va.y;
            dyA += oacc[nt][0] * va.x + oacc[nt][1] * va.y;
            svB += vb2.x * vb2.x + vb2.y * vb2.y;
            dyB += oacc[nt][2] * vb2.x + oacc[nt][3] * vb2.y;
        }
        svA += __shfl_xor_sync(0xffffffffu, svA, 1);
        svA += __shfl_xor_sync(0xffffffffu, svA, 2);
        dyA += __shfl_xor_sync(0xffffffffu, dyA, 1);
        dyA += __shfl_xor_sync(0xffffffffu, dyA, 2);
        svB += __shfl_xor_sync(0xffffffffu, svB, 1);
        svB += __shfl_xor_sync(0xffffffffu, svB, 2);
        dyB += __shfl_xor_sync(0xffffffffu, dyB, 1);
        dyB += __shfl_xor_sync(0xffffffffu, dyB, 2);
        float coefA = (dyA * invlA) / fmaxf(svA, 1e-24f);
        float coefB = (dyB * invlB) / fmaxf(svB, 1e-24f);

        __half* yA = Y + ((size_t)(b * T) + rowA) * DIM + h * HD + colb;
        __half* yB = yA + (size_t)8 * DIM;
#pragma unroll
        for (int nt = 0; nt < 16; nt++) {
            float2 va = *(const float2*)(vAp + nt * 8);
            float2 vb2 = *(const float2*)(vBp + nt * 8);
            *(__half2*)(yA + nt * 8) = __floats2half2_rn(
                oacc[nt][0] * invlA - coefA * va.x,
                oacc[nt][1] * invlA - coefA * va.y);
            *(__half2*)(yB + nt * 8) = __floats2half2_rn(
                oacc[nt][2] * invlB - coefB * vb2.x,
                oacc[nt][3] * invlB - coefB * vb2.y);
        }
    }
}

// ---------------- launch -------------------------------------------------------
extern "C" void kernel_launch(void* const* d_in, const int* in_sizes, int n_in,
                              void* d_out, int out_size)
{
    const float* x    = (const float*)d_in[0];
    const float* Wq   = (const float*)d_in[1];
    const float* Wk   = (const float*)d_in[2];
    const float* Wv   = (const float*)d_in[3];
    const float* Wp   = (const float*)d_in[4];
    const float* gain = (const float*)d_in[5];

    float *qlin, *klin, *vlin;
    __half *q, *k, *v, *y, *xh, *wqh, *wkh, *wvh, *wph;
    cudaGetSymbolAddress((void**)&qlin, g_qlin);
    cudaGetSymbolAddress((void**)&klin, g_klin);
    cudaGetSymbolAddress((void**)&vlin, g_vlin);
    cudaGetSymbolAddress((void**)&q, g_q);
    cudaGetSymbolAddress((void**)&k, g_k);
    cudaGetSymbolAddress((void**)&v, g_v);
    cudaGetSymbolAddress((void**)&y, g_y);
    cudaGetSymbolAddress((void**)&xh, g_xh);
    cudaGetSymbolAddress((void**)&wqh, g_wqh);
    cudaGetSymbolAddress((void**)&wkh, g_wkh);
    cudaGetSymbolAddress((void**)&wvh, g_wvh);
    cudaGetSymbolAddress((void**)&wph, g_wph);

    cudaFuncSetAttribute(gemm_seg, cudaFuncAttributeMaxDynamicSharedMemorySize, GEMM_SMEM);
    cudaFuncSetAttribute(flash_kernel, cudaFuncAttributeMaxDynamicSharedMemorySize, FA_SMEM);

    // 0: fused fp16 conversion
    convert_all<<<(N4X + N4Q + N4K + N4V + N4P) / 256, 256>>>(
        x, Wq, Wk, Wv, Wp, xh, wqh, wkh, wvh, wph);

    // 1: fused QKV projection (N = 2048 + 512 + 512)
    gemm_seg<<<dim3(24, MTOT / 128), 128, GEMM_SMEM>>>(
        xh, DIM,
        wqh, qlin, 16, DIM,
        wkh, klin, 4, KVH * HD,
        wvh, vlin, 4, KVH * HD);

    // 2: fused rms+rope (q,k) + v reorder -> fp16
    rope_fused<<<(NWQ + NWK + NWV) / 4, 128>>>(qlin, klin, vlin, gain, q, k, v);

    // 3: flash attention (register-resident FA2) + fused epilogue  (profiled)
    flash_kernel<<<dim3(T / 128, H, BATCH), 256, FA_SMEM>>>(q, k, v, vlin, y);

    // 4: output projection (y fp16 -> d_out fp32)
    gemm_seg<<<dim3(16, MTOT / 128), 128, GEMM_SMEM>>>(
        y, DIM,
        wph, (float*)d_out, 16, DIM,
        wph, (float*)d_out, 0, DIM,
        wph, (float*)d_out, 0, DIM);
}